// round 1
// baseline (speedup 1.0000x reference)
#include <cuda_runtime.h>

#define DIM 1024
#define S_LEN 4096
#define NH 16
#define HD 64

// Scratch (allocation-free rule: __device__ globals)
__device__ float g_Q[S_LEN * DIM];
__device__ float g_K[S_LEN * DIM];
__device__ float g_V[S_LEN * DIM];
__device__ float g_Z[S_LEN * DIM];

// ---------------------------------------------------------------------------
// C[M,N] = A[M,K] * B[N,K]^T   (both row-major, K contiguous -> NT GEMM)
// 64x64 block, BK=16, 256 threads, 4x4 per-thread tile.
// Smem staged K-transposed: As[k][m], Bs[k][n].
// ---------------------------------------------------------------------------
__global__ __launch_bounds__(256) void gemm_nt64(const float* __restrict__ A,
                                                 const float* __restrict__ B,
                                                 float* __restrict__ C,
                                                 int M, int N, int Kd) {
    __shared__ float As[16][64];
    __shared__ float Bs[16][64];
    const int bm = blockIdx.y * 64;
    const int bn = blockIdx.x * 64;
    const int t  = threadIdx.x;
    const int tx = t & 15;
    const int ty = t >> 4;
    const int lm = t >> 2;        // 0..63
    const int lk = (t & 3) * 4;   // 0,4,8,12

    float acc[4][4] = {};

    const float* Arow = A + (size_t)(bm + lm) * Kd + lk;
    const float* Brow = B + (size_t)(bn + lm) * Kd + lk;

    for (int k0 = 0; k0 < Kd; k0 += 16) {
        float4 va = *(const float4*)(Arow + k0);
        float4 vb = *(const float4*)(Brow + k0);
        As[lk + 0][lm] = va.x; As[lk + 1][lm] = va.y;
        As[lk + 2][lm] = va.z; As[lk + 3][lm] = va.w;
        Bs[lk + 0][lm] = vb.x; Bs[lk + 1][lm] = vb.y;
        Bs[lk + 2][lm] = vb.z; Bs[lk + 3][lm] = vb.w;
        __syncthreads();

#pragma unroll
        for (int kk = 0; kk < 16; kk++) {
            float4 bv = *(const float4*)&Bs[kk][tx * 4];
#pragma unroll
            for (int i = 0; i < 4; i++) {
                float a = As[kk][ty * 4 + i];
                acc[i][0] += a * bv.x;
                acc[i][1] += a * bv.y;
                acc[i][2] += a * bv.z;
                acc[i][3] += a * bv.w;
            }
        }
        __syncthreads();
    }

#pragma unroll
    for (int i = 0; i < 4; i++) {
        float4 ov = make_float4(acc[i][0], acc[i][1], acc[i][2], acc[i][3]);
        *(float4*)&C[(size_t)(bm + ty * 4 + i) * N + bn + tx * 4] = ov;
    }
}

// ---------------------------------------------------------------------------
// Causal flash attention, fp32. One block = (64 query rows) x (1 head).
// Qs/KVs/Ps = 3 x 16KB = exactly 48KB static smem.
// 256 threads (16x16), 4x4 per-thread tile both for S (m x n_keys) and O (m x d).
// Row softmax stats kept replicated across the 16-lane tx group via butterfly
// shuffles. QK^T inner loop uses d=(dd+tx)&63 rotation to avoid stride-64
// bank conflicts on the K reads.
// ---------------------------------------------------------------------------
__global__ __launch_bounds__(256) void attn64(const float* __restrict__ Q,
                                              const float* __restrict__ K,
                                              const float* __restrict__ V,
                                              float* __restrict__ Z) {
    __shared__ float Qs[64][64];
    __shared__ float KVs[64][64];
    __shared__ float Ps[64][64];

    const int qb = blockIdx.x;
    const int h  = blockIdx.y;
    const int t  = threadIdx.x;
    const int tx = t & 15;
    const int ty = t >> 4;

    // ---- load Q tile (pre-scaled by 1/sqrt(hd) = 0.125) ----
    {
        const float* Qbase = Q + (size_t)(qb * 64) * DIM + h * HD;
#pragma unroll
        for (int r = 0; r < 4; r++) {
            int id = t + r * 256;
            int n  = id >> 4;
            int d4 = (id & 15) * 4;
            float4 v = *(const float4*)(Qbase + (size_t)n * DIM + d4);
            v.x *= 0.125f; v.y *= 0.125f; v.z *= 0.125f; v.w *= 0.125f;
            *(float4*)&Qs[n][d4] = v;
        }
    }

    float o[4][4] = {};
    float mrow[4] = {-1e30f, -1e30f, -1e30f, -1e30f};
    float lrow[4] = {0.f, 0.f, 0.f, 0.f};

    for (int kb = 0; kb <= qb; kb++) {
        // ---- load K tile into KVs ----
        {
            const float* Kbase = K + (size_t)(kb * 64) * DIM + h * HD;
#pragma unroll
            for (int r = 0; r < 4; r++) {
                int id = t + r * 256;
                int n  = id >> 4;
                int d4 = (id & 15) * 4;
                *(float4*)&KVs[n][d4] = *(const float4*)(Kbase + (size_t)n * DIM + d4);
            }
        }
        __syncthreads();   // also covers the Q load on the first iteration

        // ---- S = (Q*scale) . K^T ----
        float s[4][4] = {};
#pragma unroll 8
        for (int dd = 0; dd < 64; dd++) {
            int d = (dd + tx) & 63;
            float b0 = KVs[tx * 4 + 0][d];
            float b1 = KVs[tx * 4 + 1][d];
            float b2 = KVs[tx * 4 + 2][d];
            float b3 = KVs[tx * 4 + 3][d];
#pragma unroll
            for (int i = 0; i < 4; i++) {
                float a = Qs[ty * 4 + i][d];
                s[i][0] += a * b0;
                s[i][1] += a * b1;
                s[i][2] += a * b2;
                s[i][3] += a * b3;
            }
        }

        // ---- causal mask (diagonal block only) ----
        if (kb == qb) {
#pragma unroll
            for (int i = 0; i < 4; i++)
#pragma unroll
                for (int j = 0; j < 4; j++)
                    if (tx * 4 + j > ty * 4 + i) s[i][j] = -1e30f;
        }

        // ---- online softmax update + write P tile ----
#pragma unroll
        for (int i = 0; i < 4; i++) {
            float mx = fmaxf(fmaxf(s[i][0], s[i][1]), fmaxf(s[i][2], s[i][3]));
#pragma unroll
            for (int off = 8; off >= 1; off >>= 1)
                mx = fmaxf(mx, __shfl_xor_sync(0xffffffffu, mx, off));
            float mnew  = fmaxf(mrow[i], mx);
            float scale = __expf(mrow[i] - mnew);
            mrow[i] = mnew;
            float p0 = __expf(s[i][0] - mnew);
            float p1 = __expf(s[i][1] - mnew);
            float p2 = __expf(s[i][2] - mnew);
            float p3 = __expf(s[i][3] - mnew);
            float rs = (p0 + p1) + (p2 + p3);
#pragma unroll
            for (int off = 8; off >= 1; off >>= 1)
                rs += __shfl_xor_sync(0xffffffffu, rs, off);
            lrow[i] = lrow[i] * scale + rs;
            o[i][0] *= scale; o[i][1] *= scale; o[i][2] *= scale; o[i][3] *= scale;
            *(float4*)&Ps[ty * 4 + i][tx * 4] = make_float4(p0, p1, p2, p3);
        }
        __syncthreads();   // P complete; everyone finished reading K from KVs

        // ---- load V tile into KVs ----
        {
            const float* Vbase = V + (size_t)(kb * 64) * DIM + h * HD;
#pragma unroll
            for (int r = 0; r < 4; r++) {
                int id = t + r * 256;
                int n  = id >> 4;
                int d4 = (id & 15) * 4;
                *(float4*)&KVs[n][d4] = *(const float4*)(Vbase + (size_t)n * DIM + d4);
            }
        }
        __syncthreads();

        // ---- O += P . V ----
#pragma unroll 8
        for (int k = 0; k < 64; k++) {
            float4 bv = *(const float4*)&KVs[k][tx * 4];
#pragma unroll
            for (int i = 0; i < 4; i++) {
                float a = Ps[ty * 4 + i][k];
                o[i][0] += a * bv.x;
                o[i][1] += a * bv.y;
                o[i][2] += a * bv.z;
                o[i][3] += a * bv.w;
            }
        }
        __syncthreads();   // done reading V before next iteration overwrites KVs
    }

    // ---- normalize + store Z ----
#pragma unroll
    for (int i = 0; i < 4; i++) {
        float inv = 1.0f / lrow[i];
        float4 ov = make_float4(o[i][0] * inv, o[i][1] * inv,
                                o[i][2] * inv, o[i][3] * inv);
        *(float4*)&Z[(size_t)(qb * 64 + ty * 4 + i) * DIM + h * HD + tx * 4] = ov;
    }
}

// ---------------------------------------------------------------------------
extern "C" void kernel_launch(void* const* d_in, const int* in_sizes, int n_in,
                              void* d_out, int out_size) {
    const float* x  = (const float*)d_in[0];
    const float* Wq = (const float*)d_in[1];
    const float* Wk = (const float*)d_in[2];
    const float* Wv = (const float*)d_in[3];
    const float* Wo = (const float*)d_in[4];
    float* out = (float*)d_out;

    float *dQ, *dK, *dV, *dZ;
    cudaGetSymbolAddress((void**)&dQ, g_Q);
    cudaGetSymbolAddress((void**)&dK, g_K);
    cudaGetSymbolAddress((void**)&dV, g_V);
    cudaGetSymbolAddress((void**)&dZ, g_Z);

    dim3 gproj(DIM / 64, S_LEN / 64);   // (16, 64)
    gemm_nt64<<<gproj, 256>>>(x, Wq, dQ, S_LEN, DIM, DIM);
    gemm_nt64<<<gproj, 256>>>(x, Wk, dK, S_LEN, DIM, DIM);
    gemm_nt64<<<gproj, 256>>>(x, Wv, dV, S_LEN, DIM, DIM);

    attn64<<<dim3(S_LEN / 64, NH), 256>>>(dQ, dK, dV, dZ);

    gemm_nt64<<<gproj, 256>>>(dZ, Wo, out, S_LEN, DIM, DIM);
}

// round 3
// speedup vs baseline: 1.3893x; 1.3893x over previous
#include <cuda_runtime.h>
#include <cuda_bf16.h>
#include <cstdint>

#define DIM 1024
#define S_LEN 4096
#define NH 16
#define HD 64

// Scratch (allocation-free rule: __device__ globals)
__device__ float g_Q[S_LEN * DIM];
__device__ float g_K[S_LEN * DIM];
__device__ float g_V[S_LEN * DIM];
__device__ float g_Z[S_LEN * DIM];

// ===========================================================================
// Base-ISA tensor-core helpers (compute_103-safe: ldmatrix + mma.sync)
// ===========================================================================
__device__ __forceinline__ uint32_t smem_u32(const void* p) {
    uint32_t a;
    asm("{ .reg .u64 t; cvta.to.shared.u64 t, %1; cvt.u32.u64 %0, t; }"
        : "=r"(a) : "l"(p));
    return a;
}

__device__ __forceinline__ void ldm_x4(uint32_t* f, uint32_t addr) {
    asm volatile("ldmatrix.sync.aligned.m8n8.x4.shared.b16 {%0,%1,%2,%3}, [%4];"
                 : "=r"(f[0]), "=r"(f[1]), "=r"(f[2]), "=r"(f[3]) : "r"(addr));
}
__device__ __forceinline__ void ldm_x2(uint32_t* f, uint32_t addr) {
    asm volatile("ldmatrix.sync.aligned.m8n8.x2.shared.b16 {%0,%1}, [%2];"
                 : "=r"(f[0]), "=r"(f[1]) : "r"(addr));
}
__device__ __forceinline__ void mma_bf16(float* c, const uint32_t* a,
                                         const uint32_t* b) {
    asm volatile(
        "mma.sync.aligned.m16n8k16.row.col.f32.bf16.bf16.f32 "
        "{%0,%1,%2,%3}, {%4,%5,%6,%7}, {%8,%9}, {%0,%1,%2,%3};"
        : "+f"(c[0]), "+f"(c[1]), "+f"(c[2]), "+f"(c[3])
        : "r"(a[0]), "r"(a[1]), "r"(a[2]), "r"(a[3]), "r"(b[0]), "r"(b[1]));
}

__device__ __forceinline__ uint32_t pack_bf16x2(float x, float y) {
    __nv_bfloat162 p;
    p.x = __float2bfloat16(x);
    p.y = __float2bfloat16(y);
    return *(uint32_t*)&p;
}

// ===========================================================================
// Split-bf16 tensor GEMM-NT:  C[M,N] = A[M,K] * B[N,K]^T  (fp32 in/out)
// CTA: 128x128, BK=32, 256 threads = 8 warps (2x4), warp tile 64x32.
// Smem rows padded to 40 bf16 (80B) -> conflict-free ldmatrix.
// ===========================================================================
#define RS 40                                   // padded row stride (bf16 elems)
#define SEG (128 * RS)                          // one matrix segment (elems)
#define STAGE_ELEMS (4 * SEG)                   // Ahi|Alo|Bhi|Blo
#define STAGE_BYTES (STAGE_ELEMS * 2)           // 40960
#define GEMM_SMEM (2 * STAGE_BYTES)             // 81920

__global__ __launch_bounds__(256, 1)
void gemm_mma128(const float* __restrict__ A, const float* __restrict__ B,
                 float* __restrict__ C, int M, int N, int Kd) {
    extern __shared__ __nv_bfloat16 smem[];
    const uint32_t sb = smem_u32(smem);
    const int t    = threadIdx.x;
    const int lane = t & 31;
    const int wid  = t >> 5;
    const int wm   = (wid >> 2) * 64;           // warp M offset (0/64)
    const int wn   = (wid & 3) * 32;            // warp N offset (0..96)
    const int bm   = blockIdx.y * 128;
    const int bn   = blockIdx.x * 128;

    float acc[4][4][4] = {};                    // [mt][nt][4]

    // global load mapping: 1024 float4 per matrix per chunk, 4 per thread
    const int grow = t >> 3;                    // reused row base: id>>3 for i term added
    // A/B row-major, K contiguous
    float4 pa[4], pb[4];

    auto gload = [&](int k0) {
#pragma unroll
        for (int i = 0; i < 4; i++) {
            int id  = t + i * 256;
            int row = id >> 3;
            int col = (id & 7) * 4;
            pa[i] = *(const float4*)(A + (size_t)(bm + row) * Kd + k0 + col);
            pb[i] = *(const float4*)(B + (size_t)(bn + row) * Kd + k0 + col);
        }
    };

    auto sstore = [&](int stage) {
        __nv_bfloat16* base = smem + stage * STAGE_ELEMS;
#pragma unroll
        for (int i = 0; i < 4; i++) {
            int id  = t + i * 256;
            int row = id >> 3;
            int col = (id & 7) * 4;
            int off = row * RS + col;
            float4 va = pa[i];
            float4 vb = pb[i];
            uint32_t ah0 = pack_bf16x2(va.x, va.y);
            uint32_t ah1 = pack_bf16x2(va.z, va.w);
            float rax = va.x - __bfloat162float(__float2bfloat16(va.x));
            float ray = va.y - __bfloat162float(__float2bfloat16(va.y));
            float raz = va.z - __bfloat162float(__float2bfloat16(va.z));
            float raw = va.w - __bfloat162float(__float2bfloat16(va.w));
            uint32_t al0 = pack_bf16x2(rax, ray);
            uint32_t al1 = pack_bf16x2(raz, raw);
            uint32_t bh0 = pack_bf16x2(vb.x, vb.y);
            uint32_t bh1 = pack_bf16x2(vb.z, vb.w);
            float rbx = vb.x - __bfloat162float(__float2bfloat16(vb.x));
            float rby = vb.y - __bfloat162float(__float2bfloat16(vb.y));
            float rbz = vb.z - __bfloat162float(__float2bfloat16(vb.z));
            float rbw = vb.w - __bfloat162float(__float2bfloat16(vb.w));
            uint32_t bl0 = pack_bf16x2(rbx, rby);
            uint32_t bl1 = pack_bf16x2(rbz, rbw);
            *(uint2*)(base + 0 * SEG + off) = make_uint2(ah0, ah1);
            *(uint2*)(base + 1 * SEG + off) = make_uint2(al0, al1);
            *(uint2*)(base + 2 * SEG + off) = make_uint2(bh0, bh1);
            *(uint2*)(base + 3 * SEG + off) = make_uint2(bl0, bl1);
        }
    };

    const int nchunks = Kd / 32;

    gload(0);
    sstore(0);
    __syncthreads();

    for (int c = 0; c < nchunks; c++) {
        const int stage = c & 1;
        if (c + 1 < nchunks) gload((c + 1) * 32);

        const uint32_t sstage = sb + stage * STAGE_BYTES;
        // A addr: row = wm + mt*16 + lane%16, col = (lane/16)*8 + ks*16
        const uint32_t a_base =
            sstage + ((wm + (lane & 15)) * RS + (lane >> 4) * 8) * 2;
        // B addr: row = wn + nt*8 + lane%8, col = ((lane%16)/8)*8 + ks*16
        const uint32_t b_base =
            sstage + 2 * SEG * 2 +
            ((wn + (lane & 7)) * RS + (((lane & 15) >> 3) * 8)) * 2;

#pragma unroll
        for (int ks = 0; ks < 2; ks++) {
            uint32_t ah[4][4], al[4][4], bh[4][2], bl[4][2];
#pragma unroll
            for (int mt = 0; mt < 4; mt++) {
                uint32_t addr = a_base + (mt * 16 * RS + ks * 16) * 2;
                ldm_x4(ah[mt], addr);
                ldm_x4(al[mt], addr + SEG * 2);
            }
#pragma unroll
            for (int nt = 0; nt < 4; nt++) {
                uint32_t addr = b_base + (nt * 8 * RS + ks * 16) * 2;
                ldm_x2(bh[nt], addr);
                ldm_x2(bl[nt], addr + SEG * 2);
            }
#pragma unroll
            for (int mt = 0; mt < 4; mt++)
#pragma unroll
                for (int nt = 0; nt < 4; nt++) {
                    mma_bf16(acc[mt][nt], ah[mt], bh[nt]);
                    mma_bf16(acc[mt][nt], ah[mt], bl[nt]);
                    mma_bf16(acc[mt][nt], al[mt], bh[nt]);
                }
        }
        __syncthreads();
        if (c + 1 < nchunks) {
            sstore(stage ^ 1);
            __syncthreads();
        }
    }

    // ---- epilogue: acc regs -> C ----
    const int r0 = bm + wm + (lane >> 2);
    const int c0 = bn + wn + (lane & 3) * 2;
#pragma unroll
    for (int mt = 0; mt < 4; mt++) {
#pragma unroll
        for (int nt = 0; nt < 4; nt++) {
            float* d0 = C + (size_t)(r0 + mt * 16) * N + c0 + nt * 8;
            float* d1 = d0 + 8 * N;
            *(float2*)d0 = make_float2(acc[mt][nt][0], acc[mt][nt][1]);
            *(float2*)d1 = make_float2(acc[mt][nt][2], acc[mt][nt][3]);
        }
    }
}

// ===========================================================================
// Causal flash attention, fp32 SIMT (unchanged from R1)
// ===========================================================================
__global__ __launch_bounds__(256) void attn64(const float* __restrict__ Q,
                                              const float* __restrict__ K,
                                              const float* __restrict__ V,
                                              float* __restrict__ Z) {
    __shared__ float Qs[64][64];
    __shared__ float KVs[64][64];
    __shared__ float Ps[64][64];

    const int qb = blockIdx.x;
    const int h  = blockIdx.y;
    const int t  = threadIdx.x;
    const int tx = t & 15;
    const int ty = t >> 4;

    {
        const float* Qbase = Q + (size_t)(qb * 64) * DIM + h * HD;
#pragma unroll
        for (int r = 0; r < 4; r++) {
            int id = t + r * 256;
            int n  = id >> 4;
            int d4 = (id & 15) * 4;
            float4 v = *(const float4*)(Qbase + (size_t)n * DIM + d4);
            v.x *= 0.125f; v.y *= 0.125f; v.z *= 0.125f; v.w *= 0.125f;
            *(float4*)&Qs[n][d4] = v;
        }
    }

    float o[4][4] = {};
    float mrow[4] = {-1e30f, -1e30f, -1e30f, -1e30f};
    float lrow[4] = {0.f, 0.f, 0.f, 0.f};

    for (int kb = 0; kb <= qb; kb++) {
        {
            const float* Kbase = K + (size_t)(kb * 64) * DIM + h * HD;
#pragma unroll
            for (int r = 0; r < 4; r++) {
                int id = t + r * 256;
                int n  = id >> 4;
                int d4 = (id & 15) * 4;
                *(float4*)&KVs[n][d4] = *(const float4*)(Kbase + (size_t)n * DIM + d4);
            }
        }
        __syncthreads();

        float s[4][4] = {};
#pragma unroll 8
        for (int dd = 0; dd < 64; dd++) {
            int d = (dd + tx) & 63;
            float b0 = KVs[tx * 4 + 0][d];
            float b1 = KVs[tx * 4 + 1][d];
            float b2 = KVs[tx * 4 + 2][d];
            float b3 = KVs[tx * 4 + 3][d];
#pragma unroll
            for (int i = 0; i < 4; i++) {
                float a = Qs[ty * 4 + i][d];
                s[i][0] += a * b0;
                s[i][1] += a * b1;
                s[i][2] += a * b2;
                s[i][3] += a * b3;
            }
        }

        if (kb == qb) {
#pragma unroll
            for (int i = 0; i < 4; i++)
#pragma unroll
                for (int j = 0; j < 4; j++)
                    if (tx * 4 + j > ty * 4 + i) s[i][j] = -1e30f;
        }

#pragma unroll
        for (int i = 0; i < 4; i++) {
            float mx = fmaxf(fmaxf(s[i][0], s[i][1]), fmaxf(s[i][2], s[i][3]));
#pragma unroll
            for (int off = 8; off >= 1; off >>= 1)
                mx = fmaxf(mx, __shfl_xor_sync(0xffffffffu, mx, off));
            float mnew  = fmaxf(mrow[i], mx);
            float scale = __expf(mrow[i] - mnew);
            mrow[i] = mnew;
            float p0 = __expf(s[i][0] - mnew);
            float p1 = __expf(s[i][1] - mnew);
            float p2 = __expf(s[i][2] - mnew);
            float p3 = __expf(s[i][3] - mnew);
            float rs = (p0 + p1) + (p2 + p3);
#pragma unroll
            for (int off = 8; off >= 1; off >>= 1)
                rs += __shfl_xor_sync(0xffffffffu, rs, off);
            lrow[i] = lrow[i] * scale + rs;
            o[i][0] *= scale; o[i][1] *= scale; o[i][2] *= scale; o[i][3] *= scale;
            *(float4*)&Ps[ty * 4 + i][tx * 4] = make_float4(p0, p1, p2, p3);
        }
        __syncthreads();

        {
            const float* Vbase = V + (size_t)(kb * 64) * DIM + h * HD;
#pragma unroll
            for (int r = 0; r < 4; r++) {
                int id = t + r * 256;
                int n  = id >> 4;
                int d4 = (id & 15) * 4;
                *(float4*)&KVs[n][d4] = *(const float4*)(Vbase + (size_t)n * DIM + d4);
            }
        }
        __syncthreads();

#pragma unroll 8
        for (int k = 0; k < 64; k++) {
            float4 bv = *(const float4*)&KVs[k][tx * 4];
#pragma unroll
            for (int i = 0; i < 4; i++) {
                float a = Ps[ty * 4 + i][k];
                o[i][0] += a * bv.x;
                o[i][1] += a * bv.y;
                o[i][2] += a * bv.z;
                o[i][3] += a * bv.w;
            }
        }
        __syncthreads();
    }

#pragma unroll
    for (int i = 0; i < 4; i++) {
        float inv = 1.0f / lrow[i];
        float4 ov = make_float4(o[i][0] * inv, o[i][1] * inv,
                                o[i][2] * inv, o[i][3] * inv);
        *(float4*)&Z[(size_t)(qb * 64 + ty * 4 + i) * DIM + h * HD + tx * 4] = ov;
    }
}

// ===========================================================================
extern "C" void kernel_launch(void* const* d_in, const int* in_sizes, int n_in,
                              void* d_out, int out_size) {
    const float* x  = (const float*)d_in[0];
    const float* Wq = (const float*)d_in[1];
    const float* Wk = (const float*)d_in[2];
    const float* Wv = (const float*)d_in[3];
    const float* Wo = (const float*)d_in[4];
    float* out = (float*)d_out;

    float *dQ, *dK, *dV, *dZ;
    cudaGetSymbolAddress((void**)&dQ, g_Q);
    cudaGetSymbolAddress((void**)&dK, g_K);
    cudaGetSymbolAddress((void**)&dV, g_V);
    cudaGetSymbolAddress((void**)&dZ, g_Z);

    cudaFuncSetAttribute(gemm_mma128,
                         cudaFuncAttributeMaxDynamicSharedMemorySize, GEMM_SMEM);

    dim3 gproj(DIM / 128, S_LEN / 128);   // (8, 32)
    gemm_mma128<<<gproj, 256, GEMM_SMEM>>>(x, Wq, dQ, S_LEN, DIM, DIM);
    gemm_mma128<<<gproj, 256, GEMM_SMEM>>>(x, Wk, dK, S_LEN, DIM, DIM);
    gemm_mma128<<<gproj, 256, GEMM_SMEM>>>(x, Wv, dV, S_LEN, DIM, DIM);

    attn64<<<dim3(S_LEN / 64, NH), 256>>>(dQ, dK, dV, dZ);

    gemm_mma128<<<gproj, 256, GEMM_SMEM>>>(dZ, Wo, out, S_LEN, DIM, DIM);
}

// round 5
// speedup vs baseline: 3.2723x; 2.3554x over previous
#include <cuda_runtime.h>
#include <cuda_bf16.h>
#include <cstdint>

#define DIM 1024
#define S_LEN 4096
#define NH 16
#define HD 64

// Scratch (allocation-free rule: __device__ globals)
__device__ float g_Q[S_LEN * DIM];
__device__ float g_K[S_LEN * DIM];
__device__ float g_V[S_LEN * DIM];
__device__ float g_Z[S_LEN * DIM];

// ===========================================================================
// Base-ISA tensor-core helpers (compute_103-safe: ldmatrix + mma.sync)
// ===========================================================================
__device__ __forceinline__ uint32_t smem_u32(const void* p) {
    uint32_t a;
    asm("{ .reg .u64 t; cvta.to.shared.u64 t, %1; cvt.u32.u64 %0, t; }"
        : "=r"(a) : "l"(p));
    return a;
}

__device__ __forceinline__ void ldm_x4(uint32_t* f, uint32_t addr) {
    asm volatile("ldmatrix.sync.aligned.m8n8.x4.shared.b16 {%0,%1,%2,%3}, [%4];"
                 : "=r"(f[0]), "=r"(f[1]), "=r"(f[2]), "=r"(f[3]) : "r"(addr));
}
__device__ __forceinline__ void ldm_x2(uint32_t* f, uint32_t addr) {
    asm volatile("ldmatrix.sync.aligned.m8n8.x2.shared.b16 {%0,%1}, [%2];"
                 : "=r"(f[0]), "=r"(f[1]) : "r"(addr));
}
__device__ __forceinline__ void ldm_x2t(uint32_t* f, uint32_t addr) {
    asm volatile("ldmatrix.sync.aligned.m8n8.x2.trans.shared.b16 {%0,%1}, [%2];"
                 : "=r"(f[0]), "=r"(f[1]) : "r"(addr));
}
__device__ __forceinline__ void mma_bf16(float* c, const uint32_t* a,
                                         const uint32_t* b) {
    asm volatile(
        "mma.sync.aligned.m16n8k16.row.col.f32.bf16.bf16.f32 "
        "{%0,%1,%2,%3}, {%4,%5,%6,%7}, {%8,%9}, {%0,%1,%2,%3};"
        : "+f"(c[0]), "+f"(c[1]), "+f"(c[2]), "+f"(c[3])
        : "r"(a[0]), "r"(a[1]), "r"(a[2]), "r"(a[3]), "r"(b[0]), "r"(b[1]));
}

__device__ __forceinline__ uint32_t pack_bf16x2(float x, float y) {
    __nv_bfloat162 p;
    p.x = __float2bfloat16(x);
    p.y = __float2bfloat16(y);
    return *(uint32_t*)&p;
}
__device__ __forceinline__ uint32_t pack_lo(float x, float y, uint32_t hi) {
    __nv_bfloat162 h = *(__nv_bfloat162*)&hi;
    return pack_bf16x2(x - __bfloat162float(h.x), y - __bfloat162float(h.y));
}

// ===========================================================================
// Split-bf16 tensor GEMM-NT:  C[M,N] = A[M,K] * B[N,K]^T  (fp32 in/out)
// (unchanged from R3 — passing at ~77us/launch)
// ===========================================================================
#define RS 40
#define SEG (128 * RS)
#define STAGE_ELEMS (4 * SEG)
#define STAGE_BYTES (STAGE_ELEMS * 2)
#define GEMM_SMEM (2 * STAGE_BYTES)

__global__ __launch_bounds__(256, 1)
void gemm_mma128(const float* __restrict__ A, const float* __restrict__ B,
                 float* __restrict__ C, int M, int N, int Kd) {
    extern __shared__ __nv_bfloat16 smem[];
    const uint32_t sb = smem_u32(smem);
    const int t    = threadIdx.x;
    const int lane = t & 31;
    const int wid  = t >> 5;
    const int wm   = (wid >> 2) * 64;
    const int wn   = (wid & 3) * 32;
    const int bm   = blockIdx.y * 128;
    const int bn   = blockIdx.x * 128;

    float acc[4][4][4] = {};
    float4 pa[4], pb[4];

    auto gload = [&](int k0) {
#pragma unroll
        for (int i = 0; i < 4; i++) {
            int id  = t + i * 256;
            int row = id >> 3;
            int col = (id & 7) * 4;
            pa[i] = *(const float4*)(A + (size_t)(bm + row) * Kd + k0 + col);
            pb[i] = *(const float4*)(B + (size_t)(bn + row) * Kd + k0 + col);
        }
    };

    auto sstore = [&](int stage) {
        __nv_bfloat16* base = smem + stage * STAGE_ELEMS;
#pragma unroll
        for (int i = 0; i < 4; i++) {
            int id  = t + i * 256;
            int row = id >> 3;
            int col = (id & 7) * 4;
            int off = row * RS + col;
            float4 va = pa[i];
            float4 vb = pb[i];
            uint32_t ah0 = pack_bf16x2(va.x, va.y);
            uint32_t ah1 = pack_bf16x2(va.z, va.w);
            uint32_t al0 = pack_lo(va.x, va.y, ah0);
            uint32_t al1 = pack_lo(va.z, va.w, ah1);
            uint32_t bh0 = pack_bf16x2(vb.x, vb.y);
            uint32_t bh1 = pack_bf16x2(vb.z, vb.w);
            uint32_t bl0 = pack_lo(vb.x, vb.y, bh0);
            uint32_t bl1 = pack_lo(vb.z, vb.w, bh1);
            *(uint2*)(base + 0 * SEG + off) = make_uint2(ah0, ah1);
            *(uint2*)(base + 1 * SEG + off) = make_uint2(al0, al1);
            *(uint2*)(base + 2 * SEG + off) = make_uint2(bh0, bh1);
            *(uint2*)(base + 3 * SEG + off) = make_uint2(bl0, bl1);
        }
    };

    const int nchunks = Kd / 32;
    gload(0);
    sstore(0);
    __syncthreads();

    for (int c = 0; c < nchunks; c++) {
        const int stage = c & 1;
        if (c + 1 < nchunks) gload((c + 1) * 32);

        const uint32_t sstage = sb + stage * STAGE_BYTES;
        const uint32_t a_base =
            sstage + ((wm + (lane & 15)) * RS + (lane >> 4) * 8) * 2;
        const uint32_t b_base =
            sstage + 2 * SEG * 2 +
            ((wn + (lane & 7)) * RS + (((lane & 15) >> 3) * 8)) * 2;

#pragma unroll
        for (int ks = 0; ks < 2; ks++) {
            uint32_t ah[4][4], al[4][4], bh[4][2], bl[4][2];
#pragma unroll
            for (int mt = 0; mt < 4; mt++) {
                uint32_t addr = a_base + (mt * 16 * RS + ks * 16) * 2;
                ldm_x4(ah[mt], addr);
                ldm_x4(al[mt], addr + SEG * 2);
            }
#pragma unroll
            for (int nt = 0; nt < 4; nt++) {
                uint32_t addr = b_base + (nt * 8 * RS + ks * 16) * 2;
                ldm_x2(bh[nt], addr);
                ldm_x2(bl[nt], addr + SEG * 2);
            }
#pragma unroll
            for (int mt = 0; mt < 4; mt++)
#pragma unroll
                for (int nt = 0; nt < 4; nt++) {
                    mma_bf16(acc[mt][nt], ah[mt], bh[nt]);
                    mma_bf16(acc[mt][nt], ah[mt], bl[nt]);
                    mma_bf16(acc[mt][nt], al[mt], bh[nt]);
                }
        }
        __syncthreads();
        if (c + 1 < nchunks) {
            sstore(stage ^ 1);
            __syncthreads();
        }
    }

    const int r0 = bm + wm + (lane >> 2);
    const int c0 = bn + wn + (lane & 3) * 2;
#pragma unroll
    for (int mt = 0; mt < 4; mt++) {
#pragma unroll
        for (int nt = 0; nt < 4; nt++) {
            float* d0 = C + (size_t)(r0 + mt * 16) * N + c0 + nt * 8;
            float* d1 = d0 + 8 * N;
            *(float2*)d0 = make_float2(acc[mt][nt][0], acc[mt][nt][1]);
            *(float2*)d1 = make_float2(acc[mt][nt][2], acc[mt][nt][3]);
        }
    }
}

// ===========================================================================
// Tensor-core causal flash attention, split-bf16 3-pass both matmuls.
// CTA = 128 q rows x 1 head; 8 warps x 16 rows each.
// smem rows of RS2=72 bf16: Qhi[0..127] Qlo[128..255] Khi[256..319]
//                           Klo[320..383] Vhi[384..447] Vlo[448..511]
// ===========================================================================
#define RS2 72
#define ATTN_SMEM (512 * RS2 * 2)   // 73728 bytes

#define R_QHI 0
#define R_QLO 128
#define R_KHI 256
#define R_KLO 320
#define R_VHI 384
#define R_VLO 448

__global__ __launch_bounds__(256, 1)
void attn_mma(const float* __restrict__ Q, const float* __restrict__ K,
              const float* __restrict__ V, float* __restrict__ Z) {
    extern __shared__ __nv_bfloat16 sm[];
    const uint32_t sb = smem_u32(sm);
    const int qb   = (int)gridDim.x - 1 - (int)blockIdx.x;  // big tiles first
    const int h    = blockIdx.y;
    const int t    = threadIdx.x;
    const int lane = t & 31;
    const int w    = t >> 5;

    // ---- load Q tile (scaled by 1/8), split hi/lo into smem ----
    {
        const float* Qg = Q + (size_t)(qb * 128) * DIM + h * HD;
#pragma unroll
        for (int i = 0; i < 8; i++) {
            int id   = t + i * 256;
            int row  = id >> 4;
            int col4 = (id & 15) * 4;
            float4 v = *(const float4*)(Qg + (size_t)row * DIM + col4);
            v.x *= 0.125f; v.y *= 0.125f; v.z *= 0.125f; v.w *= 0.125f;
            uint32_t h0 = pack_bf16x2(v.x, v.y);
            uint32_t h1 = pack_bf16x2(v.z, v.w);
            uint32_t l0 = pack_lo(v.x, v.y, h0);
            uint32_t l1 = pack_lo(v.z, v.w, h1);
            int off = row * RS2 + col4;
            *(uint2*)(sm + R_QHI * RS2 + off) = make_uint2(h0, h1);
            *(uint2*)(sm + R_QLO * RS2 + off) = make_uint2(l0, l1);
        }
    }
    __syncthreads();

    // ---- per-warp Q fragments (kept in registers for all kb) ----
    uint32_t qh[4][4], ql[4][4];
#pragma unroll
    for (int ks = 0; ks < 4; ks++) {
        uint32_t addr = sb +
            ((w * 16 + (lane & 15)) * RS2 + ks * 16 + (lane >> 4) * 8) * 2;
        ldm_x4(qh[ks], addr);
        ldm_x4(ql[ks], addr + R_QLO * RS2 * 2);
    }

    float o[8][4] = {};
    float m0 = -1e30f, m1 = -1e30f, l0 = 0.f, l1 = 0.f;
    const int row0 = qb * 128 + w * 16 + (lane >> 2);

    const int nkb = 2 * qb + 2;
    for (int kb = 0; kb < nkb; kb++) {
        // ---- load K/V tiles (64 x 64), split hi/lo ----
        const float* Kg = K + (size_t)(kb * 64) * DIM + h * HD;
        const float* Vg = V + (size_t)(kb * 64) * DIM + h * HD;
#pragma unroll
        for (int i = 0; i < 4; i++) {
            int id   = t + i * 256;
            int row  = id >> 4;
            int col4 = (id & 15) * 4;
            int off  = row * RS2 + col4;
            float4 v = *(const float4*)(Kg + (size_t)row * DIM + col4);
            uint32_t h0 = pack_bf16x2(v.x, v.y);
            uint32_t h1 = pack_bf16x2(v.z, v.w);
            *(uint2*)(sm + R_KHI * RS2 + off) = make_uint2(h0, h1);
            *(uint2*)(sm + R_KLO * RS2 + off) =
                make_uint2(pack_lo(v.x, v.y, h0), pack_lo(v.z, v.w, h1));
            float4 u = *(const float4*)(Vg + (size_t)row * DIM + col4);
            uint32_t g0 = pack_bf16x2(u.x, u.y);
            uint32_t g1 = pack_bf16x2(u.z, u.w);
            *(uint2*)(sm + R_VHI * RS2 + off) = make_uint2(g0, g1);
            *(uint2*)(sm + R_VLO * RS2 + off) =
                make_uint2(pack_lo(u.x, u.y, g0), pack_lo(u.z, u.w, g1));
        }
        __syncthreads();

        // warp fully below the diagonal band? (all its rows masked)
        const bool active = (kb * 64 <= qb * 128 + w * 16 + 15);
        if (active) {
            // ---- S = Q K^T (3-pass split) ----
            float c[8][4] = {};
#pragma unroll
            for (int ks = 0; ks < 4; ks++) {
#pragma unroll
                for (int nt = 0; nt < 8; nt++) {
                    uint32_t bh[2], bl[2];
                    uint32_t addr = sb +
                        ((R_KHI + nt * 8 + (lane & 7)) * RS2 +
                         ks * 16 + ((lane >> 3) & 1) * 8) * 2;
                    ldm_x2(bh, addr);
                    ldm_x2(bl, addr + 64 * RS2 * 2);
                    mma_bf16(c[nt], qh[ks], bh);
                    mma_bf16(c[nt], qh[ks], bl);
                    mma_bf16(c[nt], ql[ks], bh);
                }
            }

            // ---- causal mask (only near-diagonal blocks) ----
            if (kb * 64 + 63 > row0) {
                const int colbase = kb * 64 + (lane & 3) * 2;
#pragma unroll
                for (int nt = 0; nt < 8; nt++) {
                    int cc = colbase + nt * 8;
                    if (cc     > row0)     c[nt][0] = -1e30f;
                    if (cc + 1 > row0)     c[nt][1] = -1e30f;
                    if (cc     > row0 + 8) c[nt][2] = -1e30f;
                    if (cc + 1 > row0 + 8) c[nt][3] = -1e30f;
                }
            }

            // ---- online softmax (rows shared by 4-lane groups) ----
            float mx0 = -1e30f, mx1 = -1e30f;
#pragma unroll
            for (int nt = 0; nt < 8; nt++) {
                mx0 = fmaxf(mx0, fmaxf(c[nt][0], c[nt][1]));
                mx1 = fmaxf(mx1, fmaxf(c[nt][2], c[nt][3]));
            }
            mx0 = fmaxf(mx0, __shfl_xor_sync(0xffffffffu, mx0, 1));
            mx0 = fmaxf(mx0, __shfl_xor_sync(0xffffffffu, mx0, 2));
            mx1 = fmaxf(mx1, __shfl_xor_sync(0xffffffffu, mx1, 1));
            mx1 = fmaxf(mx1, __shfl_xor_sync(0xffffffffu, mx1, 2));
            float M0 = fmaxf(m0, mx0);
            float M1 = fmaxf(m1, mx1);
            float sc0 = __expf(m0 - M0);
            float sc1 = __expf(m1 - M1);
            m0 = M0; m1 = M1;
            float s0 = 0.f, s1 = 0.f;
#pragma unroll
            for (int nt = 0; nt < 8; nt++) {
                c[nt][0] = __expf(c[nt][0] - M0);
                c[nt][1] = __expf(c[nt][1] - M0);
                c[nt][2] = __expf(c[nt][2] - M1);
                c[nt][3] = __expf(c[nt][3] - M1);
                s0 += c[nt][0] + c[nt][1];
                s1 += c[nt][2] + c[nt][3];
            }
            s0 += __shfl_xor_sync(0xffffffffu, s0, 1);
            s0 += __shfl_xor_sync(0xffffffffu, s0, 2);
            s1 += __shfl_xor_sync(0xffffffffu, s1, 1);
            s1 += __shfl_xor_sync(0xffffffffu, s1, 2);
            l0 = l0 * sc0 + s0;
            l1 = l1 * sc1 + s1;
#pragma unroll
            for (int nt = 0; nt < 8; nt++) {
                o[nt][0] *= sc0; o[nt][1] *= sc0;
                o[nt][2] *= sc1; o[nt][3] *= sc1;
            }

            // ---- O += P V (3-pass split; P stays in registers) ----
#pragma unroll
            for (int ks = 0; ks < 4; ks++) {
                uint32_t ah[4], al[4];
                ah[0] = pack_bf16x2(c[2 * ks][0],     c[2 * ks][1]);
                ah[1] = pack_bf16x2(c[2 * ks][2],     c[2 * ks][3]);
                ah[2] = pack_bf16x2(c[2 * ks + 1][0], c[2 * ks + 1][1]);
                ah[3] = pack_bf16x2(c[2 * ks + 1][2], c[2 * ks + 1][3]);
                al[0] = pack_lo(c[2 * ks][0],     c[2 * ks][1],     ah[0]);
                al[1] = pack_lo(c[2 * ks][2],     c[2 * ks][3],     ah[1]);
                al[2] = pack_lo(c[2 * ks + 1][0], c[2 * ks + 1][1], ah[2]);
                al[3] = pack_lo(c[2 * ks + 1][2], c[2 * ks + 1][3], ah[3]);
#pragma unroll
                for (int nt = 0; nt < 8; nt++) {
                    uint32_t vh[2], vl[2];
                    uint32_t addr = sb +
                        ((R_VHI + ks * 16 + (lane & 15)) * RS2 + nt * 8) * 2;
                    ldm_x2t(vh, addr);
                    ldm_x2t(vl, addr + 64 * RS2 * 2);
                    mma_bf16(o[nt], ah, vh);
                    mma_bf16(o[nt], ah, vl);
                    mma_bf16(o[nt], al, vh);
                }
            }
        }
        __syncthreads();
    }

    // ---- normalize + store ----
    const float inv0 = 1.0f / l0;
    const float inv1 = 1.0f / l1;
    float* z0 = Z + (size_t)row0 * DIM + h * HD + (lane & 3) * 2;
#pragma unroll
    for (int nt = 0; nt < 8; nt++) {
        *(float2*)(z0 + nt * 8) =
            make_float2(o[nt][0] * inv0, o[nt][1] * inv0);
        *(float2*)(z0 + (size_t)8 * DIM + nt * 8) =
            make_float2(o[nt][2] * inv1, o[nt][3] * inv1);
    }
}

// ===========================================================================
extern "C" void kernel_launch(void* const* d_in, const int* in_sizes, int n_in,
                              void* d_out, int out_size) {
    const float* x  = (const float*)d_in[0];
    const float* Wq = (const float*)d_in[1];
    const float* Wk = (const float*)d_in[2];
    const float* Wv = (const float*)d_in[3];
    const float* Wo = (const float*)d_in[4];
    float* out = (float*)d_out;

    float *dQ, *dK, *dV, *dZ;
    cudaGetSymbolAddress((void**)&dQ, g_Q);
    cudaGetSymbolAddress((void**)&dK, g_K);
    cudaGetSymbolAddress((void**)&dV, g_V);
    cudaGetSymbolAddress((void**)&dZ, g_Z);

    cudaFuncSetAttribute(gemm_mma128,
                         cudaFuncAttributeMaxDynamicSharedMemorySize, GEMM_SMEM);
    cudaFuncSetAttribute(attn_mma,
                         cudaFuncAttributeMaxDynamicSharedMemorySize, ATTN_SMEM);

    dim3 gproj(DIM / 128, S_LEN / 128);   // (8, 32)
    gemm_mma128<<<gproj, 256, GEMM_SMEM>>>(x, Wq, dQ, S_LEN, DIM, DIM);
    gemm_mma128<<<gproj, 256, GEMM_SMEM>>>(x, Wk, dK, S_LEN, DIM, DIM);
    gemm_mma128<<<gproj, 256, GEMM_SMEM>>>(x, Wv, dV, S_LEN, DIM, DIM);

    attn_mma<<<dim3(S_LEN / 128, NH), 256, ATTN_SMEM>>>(dQ, dK, dV, dZ);

    gemm_mma128<<<gproj, 256, GEMM_SMEM>>>(dZ, Wo, out, S_LEN, DIM, DIM);
}

// round 6
// speedup vs baseline: 3.3615x; 1.0273x over previous
#include <cuda_runtime.h>
#include <cuda_bf16.h>
#include <cstdint>

#define DIM 1024
#define S_LEN 4096
#define NH 16
#define HD 64

// Scratch (allocation-free rule: __device__ globals)
__device__ __nv_bfloat16 g_Qh[S_LEN * DIM];
__device__ __nv_bfloat16 g_Ql[S_LEN * DIM];
__device__ __nv_bfloat16 g_Kh[S_LEN * DIM];
__device__ __nv_bfloat16 g_Kl[S_LEN * DIM];
__device__ __nv_bfloat16 g_Vh[S_LEN * DIM];
__device__ __nv_bfloat16 g_Vl[S_LEN * DIM];
__device__ float g_Z[S_LEN * DIM];

// ===========================================================================
// Base-ISA tensor-core helpers (compute_103-safe: ldmatrix + mma.sync)
// ===========================================================================
__device__ __forceinline__ uint32_t smem_u32(const void* p) {
    uint32_t a;
    asm("{ .reg .u64 t; cvta.to.shared.u64 t, %1; cvt.u32.u64 %0, t; }"
        : "=r"(a) : "l"(p));
    return a;
}

__device__ __forceinline__ void ldm_x4(uint32_t* f, uint32_t addr) {
    asm volatile("ldmatrix.sync.aligned.m8n8.x4.shared.b16 {%0,%1,%2,%3}, [%4];"
                 : "=r"(f[0]), "=r"(f[1]), "=r"(f[2]), "=r"(f[3]) : "r"(addr));
}
__device__ __forceinline__ void ldm_x4t(uint32_t* f, uint32_t addr) {
    asm volatile("ldmatrix.sync.aligned.m8n8.x4.trans.shared.b16 {%0,%1,%2,%3}, [%4];"
                 : "=r"(f[0]), "=r"(f[1]), "=r"(f[2]), "=r"(f[3]) : "r"(addr));
}
__device__ __forceinline__ void ldm_x2(uint32_t* f, uint32_t addr) {
    asm volatile("ldmatrix.sync.aligned.m8n8.x2.shared.b16 {%0,%1}, [%2];"
                 : "=r"(f[0]), "=r"(f[1]) : "r"(addr));
}
__device__ __forceinline__ void mma_bf16(float* c, const uint32_t* a,
                                         const uint32_t* b) {
    asm volatile(
        "mma.sync.aligned.m16n8k16.row.col.f32.bf16.bf16.f32 "
        "{%0,%1,%2,%3}, {%4,%5,%6,%7}, {%8,%9}, {%0,%1,%2,%3};"
        : "+f"(c[0]), "+f"(c[1]), "+f"(c[2]), "+f"(c[3])
        : "r"(a[0]), "r"(a[1]), "r"(a[2]), "r"(a[3]), "r"(b[0]), "r"(b[1]));
}

__device__ __forceinline__ uint32_t pack_bf16x2(float x, float y) {
    __nv_bfloat162 p;
    p.x = __float2bfloat16(x);
    p.y = __float2bfloat16(y);
    return *(uint32_t*)&p;
}
__device__ __forceinline__ uint32_t pack_lo(float x, float y, uint32_t hi) {
    __nv_bfloat162 h = *(__nv_bfloat162*)&hi;
    return pack_bf16x2(x - __bfloat162float(h.x), y - __bfloat162float(h.y));
}

#define CP_ASYNC16(dst, src)                                                   \
    asm volatile("cp.async.cg.shared.global [%0], [%1], 16;"                   \
                 :: "r"(dst), "l"(src))
#define CP_COMMIT() asm volatile("cp.async.commit_group;" ::: "memory")
#define CP_WAIT0()  asm volatile("cp.async.wait_group 0;" ::: "memory")

// ===========================================================================
// Split-bf16 tensor GEMM-NT:  C = A * B^T  (A,B fp32 row-major, K contig)
// Output: either fp32 C, or split-bf16 (Chi, Clo) with scale folded in.
// ===========================================================================
#define RS 40
#define SEG (128 * RS)
#define STAGE_ELEMS (4 * SEG)
#define STAGE_BYTES (STAGE_ELEMS * 2)
#define GEMM_SMEM (2 * STAGE_BYTES)

__global__ __launch_bounds__(256, 1)
void gemm_mma128(const float* __restrict__ A, const float* __restrict__ B,
                 float* __restrict__ C, __nv_bfloat16* __restrict__ Chi,
                 __nv_bfloat16* __restrict__ Clo, float scale,
                 int M, int N, int Kd) {
    extern __shared__ __nv_bfloat16 smem[];
    const uint32_t sb = smem_u32(smem);
    const int t    = threadIdx.x;
    const int lane = t & 31;
    const int wid  = t >> 5;
    const int wm   = (wid >> 2) * 64;
    const int wn   = (wid & 3) * 32;
    const int bm   = blockIdx.y * 128;
    const int bn   = blockIdx.x * 128;

    float acc[4][4][4] = {};
    float4 pa[4], pb[4];

    auto gload = [&](int k0) {
#pragma unroll
        for (int i = 0; i < 4; i++) {
            int id  = t + i * 256;
            int row = id >> 3;
            int col = (id & 7) * 4;
            pa[i] = *(const float4*)(A + (size_t)(bm + row) * Kd + k0 + col);
            pb[i] = *(const float4*)(B + (size_t)(bn + row) * Kd + k0 + col);
        }
    };

    auto sstore = [&](int stage) {
        __nv_bfloat16* base = smem + stage * STAGE_ELEMS;
#pragma unroll
        for (int i = 0; i < 4; i++) {
            int id  = t + i * 256;
            int row = id >> 3;
            int col = (id & 7) * 4;
            int off = row * RS + col;
            float4 va = pa[i];
            float4 vb = pb[i];
            uint32_t ah0 = pack_bf16x2(va.x, va.y);
            uint32_t ah1 = pack_bf16x2(va.z, va.w);
            uint32_t al0 = pack_lo(va.x, va.y, ah0);
            uint32_t al1 = pack_lo(va.z, va.w, ah1);
            uint32_t bh0 = pack_bf16x2(vb.x, vb.y);
            uint32_t bh1 = pack_bf16x2(vb.z, vb.w);
            uint32_t bl0 = pack_lo(vb.x, vb.y, bh0);
            uint32_t bl1 = pack_lo(vb.z, vb.w, bh1);
            *(uint2*)(base + 0 * SEG + off) = make_uint2(ah0, ah1);
            *(uint2*)(base + 1 * SEG + off) = make_uint2(al0, al1);
            *(uint2*)(base + 2 * SEG + off) = make_uint2(bh0, bh1);
            *(uint2*)(base + 3 * SEG + off) = make_uint2(bl0, bl1);
        }
    };

    const int nchunks = Kd / 32;
    gload(0);
    sstore(0);
    __syncthreads();

    for (int c = 0; c < nchunks; c++) {
        const int stage = c & 1;
        if (c + 1 < nchunks) gload((c + 1) * 32);

        const uint32_t sstage = sb + stage * STAGE_BYTES;
        const uint32_t a_base =
            sstage + ((wm + (lane & 15)) * RS + (lane >> 4) * 8) * 2;
        const uint32_t b_base =
            sstage + 2 * SEG * 2 +
            ((wn + (lane & 7)) * RS + (((lane & 15) >> 3) * 8)) * 2;

#pragma unroll
        for (int ks = 0; ks < 2; ks++) {
            uint32_t ah[4][4], al[4][4], bh[4][2], bl[4][2];
#pragma unroll
            for (int mt = 0; mt < 4; mt++) {
                uint32_t addr = a_base + (mt * 16 * RS + ks * 16) * 2;
                ldm_x4(ah[mt], addr);
                ldm_x4(al[mt], addr + SEG * 2);
            }
#pragma unroll
            for (int nt = 0; nt < 4; nt++) {
                uint32_t addr = b_base + (nt * 8 * RS + ks * 16) * 2;
                ldm_x2(bh[nt], addr);
                ldm_x2(bl[nt], addr + SEG * 2);
            }
#pragma unroll
            for (int mt = 0; mt < 4; mt++)
#pragma unroll
                for (int nt = 0; nt < 4; nt++) {
                    mma_bf16(acc[mt][nt], ah[mt], bh[nt]);
                    mma_bf16(acc[mt][nt], ah[mt], bl[nt]);
                    mma_bf16(acc[mt][nt], al[mt], bh[nt]);
                }
        }
        __syncthreads();
        if (c + 1 < nchunks) {
            sstore(stage ^ 1);
            __syncthreads();
        }
    }

    const int r0 = bm + wm + (lane >> 2);
    const int c0 = bn + wn + (lane & 3) * 2;
    if (C) {
#pragma unroll
        for (int mt = 0; mt < 4; mt++)
#pragma unroll
            for (int nt = 0; nt < 4; nt++) {
                float* d0 = C + (size_t)(r0 + mt * 16) * N + c0 + nt * 8;
                float* d1 = d0 + 8 * N;
                *(float2*)d0 = make_float2(acc[mt][nt][0], acc[mt][nt][1]);
                *(float2*)d1 = make_float2(acc[mt][nt][2], acc[mt][nt][3]);
            }
    } else {
#pragma unroll
        for (int mt = 0; mt < 4; mt++)
#pragma unroll
            for (int nt = 0; nt < 4; nt++) {
                float v0 = acc[mt][nt][0] * scale;
                float v1 = acc[mt][nt][1] * scale;
                float v2 = acc[mt][nt][2] * scale;
                float v3 = acc[mt][nt][3] * scale;
                uint32_t h01 = pack_bf16x2(v0, v1);
                uint32_t l01 = pack_lo(v0, v1, h01);
                uint32_t h23 = pack_bf16x2(v2, v3);
                uint32_t l23 = pack_lo(v2, v3, h23);
                size_t o0 = (size_t)(r0 + mt * 16) * N + c0 + nt * 8;
                size_t o1 = o0 + (size_t)8 * N;
                *(uint32_t*)(Chi + o0) = h01;
                *(uint32_t*)(Clo + o0) = l01;
                *(uint32_t*)(Chi + o1) = h23;
                *(uint32_t*)(Clo + o1) = l23;
            }
    }
}

// ===========================================================================
// Tensor-core causal flash attention, pre-split bf16 inputs, cp.async
// double-buffered K/V, one __syncthreads per tile.
// CTA = 128 q rows x 1 head; 8 warps x 16 rows.
// smem rows (RS2=72 bf16 each):
//   [0..127]   Qhi     [128..255] Qlo
//   stage s at 256+s*256:  Khi(64) Klo(64) Vhi(64) Vlo(64)
// ===========================================================================
#define RS2 72
#define ATTN_SMEM (768 * RS2 * 2)   // 110592 bytes

__global__ __launch_bounds__(256, 1)
void attn_mma(const __nv_bfloat16* __restrict__ Qh,
              const __nv_bfloat16* __restrict__ Ql,
              const __nv_bfloat16* __restrict__ Kh,
              const __nv_bfloat16* __restrict__ Kl,
              const __nv_bfloat16* __restrict__ Vh,
              const __nv_bfloat16* __restrict__ Vl,
              float* __restrict__ Z) {
    extern __shared__ __nv_bfloat16 sm[];
    const uint32_t sb = smem_u32(sm);
    const int qb   = (int)gridDim.x - 1 - (int)blockIdx.x;  // big tiles first
    const int h    = blockIdx.y;
    const int t    = threadIdx.x;
    const int lane = t & 31;
    const int w    = t >> 5;

    // ---- cp.async issue for one K/V stage (64x64 x 4 matrices) ----
    auto issue_kv = [&](int kb, int s) {
        const __nv_bfloat16* bases[4] = {Kh, Kl, Vh, Vl};
        const int r_lo = t >> 3;
        const int c8   = (t & 7) * 8;
#pragma unroll
        for (int i = 0; i < 8; i++) {
            int mtx = i >> 1;
            int r   = (i & 1) * 32 + r_lo;
            const __nv_bfloat16* src =
                bases[mtx] + (size_t)(kb * 64 + r) * DIM + h * 64 + c8;
            uint32_t dst =
                sb + ((256 + s * 256 + mtx * 64 + r) * RS2 + c8) * 2;
            CP_ASYNC16(dst, src);
        }
    };

    // ---- prologue: Q (hi+lo) + stage 0 K/V ----
    {
        const int c8 = (t & 7) * 8;
#pragma unroll
        for (int i = 0; i < 8; i++) {
            int id  = t + i * 256;
            int buf = id >> 10;               // 0 = hi, 1 = lo
            int r   = (id & 1023) >> 3;       // 0..127
            const __nv_bfloat16* src =
                (buf ? Ql : Qh) + (size_t)(qb * 128 + r) * DIM + h * 64 + c8;
            uint32_t dst = sb + ((buf * 128 + r) * RS2 + c8) * 2;
            CP_ASYNC16(dst, src);
        }
        issue_kv(0, 0);
        CP_COMMIT();
        CP_WAIT0();
    }
    __syncthreads();

    // ---- per-warp Q fragments (held in registers for all kb) ----
    uint32_t qh[4][4], ql[4][4];
#pragma unroll
    for (int ks = 0; ks < 4; ks++) {
        uint32_t addr = sb +
            ((w * 16 + (lane & 15)) * RS2 + ks * 16 + (lane >> 4) * 8) * 2;
        ldm_x4(qh[ks], addr);
        ldm_x4(ql[ks], addr + 128 * RS2 * 2);
    }

    float o[8][4] = {};
    float m0 = -1e30f, m1 = -1e30f, l0 = 0.f, l1 = 0.f;
    const int row0 = qb * 128 + w * 16 + (lane >> 2);

    const int nkb = 2 * qb + 2;
    for (int kb = 0; kb < nkb; kb++) {
        const int s = kb & 1;
        if (kb + 1 < nkb) { issue_kv(kb + 1, s ^ 1); CP_COMMIT(); }

        const bool active = (kb * 64 <= qb * 128 + w * 16 + 15);
        if (active) {
            const int KB = 256 + s * 256;        // Khi rows
            const int VB = KB + 128;             // Vhi rows

            // ---- S = Q K^T (3-pass split; x4 ldmatrix = 2 nt per load) ----
            float c[8][4] = {};
#pragma unroll
            for (int ks = 0; ks < 4; ks++) {
#pragma unroll
                for (int ntp = 0; ntp < 4; ntp++) {
                    uint32_t fh[4], fl[4];
                    uint32_t addr = sb +
                        ((KB + ntp * 16 + (lane & 15)) * RS2 +
                         ks * 16 + (lane >> 4) * 8) * 2;
                    ldm_x4(fh, addr);
                    ldm_x4(fl, addr + 64 * RS2 * 2);
                    uint32_t beh[2] = {fh[0], fh[2]}, bel[2] = {fl[0], fl[2]};
                    uint32_t boh[2] = {fh[1], fh[3]}, bol[2] = {fl[1], fl[3]};
                    mma_bf16(c[2 * ntp],     qh[ks], beh);
                    mma_bf16(c[2 * ntp],     qh[ks], bel);
                    mma_bf16(c[2 * ntp],     ql[ks], beh);
                    mma_bf16(c[2 * ntp + 1], qh[ks], boh);
                    mma_bf16(c[2 * ntp + 1], qh[ks], bol);
                    mma_bf16(c[2 * ntp + 1], ql[ks], boh);
                }
            }

            // ---- causal mask (near-diagonal blocks only) ----
            if (kb * 64 + 63 > row0) {
                const int colbase = kb * 64 + (lane & 3) * 2;
#pragma unroll
                for (int nt = 0; nt < 8; nt++) {
                    int cc = colbase + nt * 8;
                    if (cc     > row0)     c[nt][0] = -1e30f;
                    if (cc + 1 > row0)     c[nt][1] = -1e30f;
                    if (cc     > row0 + 8) c[nt][2] = -1e30f;
                    if (cc + 1 > row0 + 8) c[nt][3] = -1e30f;
                }
            }

            // ---- online softmax ----
            float mx0 = -1e30f, mx1 = -1e30f;
#pragma unroll
            for (int nt = 0; nt < 8; nt++) {
                mx0 = fmaxf(mx0, fmaxf(c[nt][0], c[nt][1]));
                mx1 = fmaxf(mx1, fmaxf(c[nt][2], c[nt][3]));
            }
            mx0 = fmaxf(mx0, __shfl_xor_sync(0xffffffffu, mx0, 1));
            mx0 = fmaxf(mx0, __shfl_xor_sync(0xffffffffu, mx0, 2));
            mx1 = fmaxf(mx1, __shfl_xor_sync(0xffffffffu, mx1, 1));
            mx1 = fmaxf(mx1, __shfl_xor_sync(0xffffffffu, mx1, 2));
            float M0 = fmaxf(m0, mx0);
            float M1 = fmaxf(m1, mx1);
            float sc0 = __expf(m0 - M0);
            float sc1 = __expf(m1 - M1);
            m0 = M0; m1 = M1;
            float s0 = 0.f, s1 = 0.f;
#pragma unroll
            for (int nt = 0; nt < 8; nt++) {
                c[nt][0] = __expf(c[nt][0] - M0);
                c[nt][1] = __expf(c[nt][1] - M0);
                c[nt][2] = __expf(c[nt][2] - M1);
                c[nt][3] = __expf(c[nt][3] - M1);
                s0 += c[nt][0] + c[nt][1];
                s1 += c[nt][2] + c[nt][3];
            }
            s0 += __shfl_xor_sync(0xffffffffu, s0, 1);
            s0 += __shfl_xor_sync(0xffffffffu, s0, 2);
            s1 += __shfl_xor_sync(0xffffffffu, s1, 1);
            s1 += __shfl_xor_sync(0xffffffffu, s1, 2);
            l0 = l0 * sc0 + s0;
            l1 = l1 * sc1 + s1;
#pragma unroll
            for (int nt = 0; nt < 8; nt++) {
                o[nt][0] *= sc0; o[nt][1] *= sc0;
                o[nt][2] *= sc1; o[nt][3] *= sc1;
            }

            // ---- O += P V (3-pass split; x4.trans = 2 nt per load) ----
#pragma unroll
            for (int ks = 0; ks < 4; ks++) {
                uint32_t ah[4], al[4];
                ah[0] = pack_bf16x2(c[2 * ks][0],     c[2 * ks][1]);
                ah[1] = pack_bf16x2(c[2 * ks][2],     c[2 * ks][3]);
                ah[2] = pack_bf16x2(c[2 * ks + 1][0], c[2 * ks + 1][1]);
                ah[3] = pack_bf16x2(c[2 * ks + 1][2], c[2 * ks + 1][3]);
                al[0] = pack_lo(c[2 * ks][0],     c[2 * ks][1],     ah[0]);
                al[1] = pack_lo(c[2 * ks][2],     c[2 * ks][3],     ah[1]);
                al[2] = pack_lo(c[2 * ks + 1][0], c[2 * ks + 1][1], ah[2]);
                al[3] = pack_lo(c[2 * ks + 1][2], c[2 * ks + 1][3], ah[3]);
#pragma unroll
                for (int ntp = 0; ntp < 4; ntp++) {
                    uint32_t fh[4], fl[4];
                    uint32_t addr = sb +
                        ((VB + ks * 16 + (lane & 15)) * RS2 +
                         ntp * 16 + (lane >> 4) * 8) * 2;
                    ldm_x4t(fh, addr);
                    ldm_x4t(fl, addr + 64 * RS2 * 2);
                    uint32_t veh[2] = {fh[0], fh[1]}, vel[2] = {fl[0], fl[1]};
                    uint32_t voh[2] = {fh[2], fh[3]}, vol[2] = {fl[2], fl[3]};
                    mma_bf16(o[2 * ntp],     ah, veh);
                    mma_bf16(o[2 * ntp],     ah, vel);
                    mma_bf16(o[2 * ntp],     al, veh);
                    mma_bf16(o[2 * ntp + 1], ah, voh);
                    mma_bf16(o[2 * ntp + 1], ah, vol);
                    mma_bf16(o[2 * ntp + 1], al, voh);
                }
            }
        }
        if (kb + 1 < nkb) CP_WAIT0();
        __syncthreads();
    }

    // ---- normalize + store ----
    const float inv0 = 1.0f / l0;
    const float inv1 = 1.0f / l1;
    float* z0 = Z + (size_t)row0 * DIM + h * HD + (lane & 3) * 2;
#pragma unroll
    for (int nt = 0; nt < 8; nt++) {
        *(float2*)(z0 + nt * 8) =
            make_float2(o[nt][0] * inv0, o[nt][1] * inv0);
        *(float2*)(z0 + (size_t)8 * DIM + nt * 8) =
            make_float2(o[nt][2] * inv1, o[nt][3] * inv1);
    }
}

// ===========================================================================
extern "C" void kernel_launch(void* const* d_in, const int* in_sizes, int n_in,
                              void* d_out, int out_size) {
    const float* x  = (const float*)d_in[0];
    const float* Wq = (const float*)d_in[1];
    const float* Wk = (const float*)d_in[2];
    const float* Wv = (const float*)d_in[3];
    const float* Wo = (const float*)d_in[4];
    float* out = (float*)d_out;

    __nv_bfloat16 *dQh, *dQl, *dKh, *dKl, *dVh, *dVl;
    float* dZ;
    cudaGetSymbolAddress((void**)&dQh, g_Qh);
    cudaGetSymbolAddress((void**)&dQl, g_Ql);
    cudaGetSymbolAddress((void**)&dKh, g_Kh);
    cudaGetSymbolAddress((void**)&dKl, g_Kl);
    cudaGetSymbolAddress((void**)&dVh, g_Vh);
    cudaGetSymbolAddress((void**)&dVl, g_Vl);
    cudaGetSymbolAddress((void**)&dZ, g_Z);

    cudaFuncSetAttribute(gemm_mma128,
                         cudaFuncAttributeMaxDynamicSharedMemorySize, GEMM_SMEM);
    cudaFuncSetAttribute(attn_mma,
                         cudaFuncAttributeMaxDynamicSharedMemorySize, ATTN_SMEM);

    dim3 gproj(DIM / 128, S_LEN / 128);   // (8, 32)
    gemm_mma128<<<gproj, 256, GEMM_SMEM>>>(x, Wq, nullptr, dQh, dQl, 0.125f,
                                           S_LEN, DIM, DIM);
    gemm_mma128<<<gproj, 256, GEMM_SMEM>>>(x, Wk, nullptr, dKh, dKl, 1.0f,
                                           S_LEN, DIM, DIM);
    gemm_mma128<<<gproj, 256, GEMM_SMEM>>>(x, Wv, nullptr, dVh, dVl, 1.0f,
                                           S_LEN, DIM, DIM);

    attn_mma<<<dim3(S_LEN / 128, NH), 256, ATTN_SMEM>>>(dQh, dQl, dKh, dKl,
                                                        dVh, dVl, dZ);

    gemm_mma128<<<gproj, 256, GEMM_SMEM>>>(dZ, Wo, out, nullptr, nullptr, 1.0f,
                                           S_LEN, DIM, DIM);
}